// round 1
// baseline (speedup 1.0000x reference)
#include <cuda_runtime.h>

// YOLO detection-head decode:
//   in : (64, 3*85, 52, 52) f32, channel-major, spatial contiguous
//   out: (64, 3*2704, 85)  f32, attr-last contiguous
// Pure transpose + elementwise (sigmoid / exp*anchor / +grid, *stride).
// HBM-bound: ~353 MB compulsory traffic. Strategy: smem tile transpose so
// both global read and global write are float4-coalesced.

#define GDIM        52
#define SPATIAL     2704          // 52*52
#define NATTR       85
#define S_TILE      104           // 2 grid rows; 2704/104 = 26 exact
#define TILES       26
#define NTHREADS    256
#define SMEM_LD     105           // 105 % 32 = 9, gcd(9,32)=1 -> conflict-free

__global__ __launch_bounds__(NTHREADS)
void yolo_decode_kernel(const float* __restrict__ in, float* __restrict__ out) {
    __shared__ float sm[NATTR * SMEM_LD];   // 35.7 KB

    const int blk   = blockIdx.x;
    const int tile  = blk % TILES;
    const int plane = blk / TILES;          // b*3 + a
    const int a     = plane % 3;

    // anchors already multiplied by stride (stride=8, anchors/stride*stride = anchors in px)
    const float aw = (a == 0) ? 10.0f : (a == 1) ? 16.0f : 33.0f;
    const float ah = (a == 0) ? 13.0f : (a == 1) ? 30.0f : 23.0f;

    const int s0 = tile * S_TILE;
    const int y0 = tile * 2;                // s0 / 52

    const float* inp = in + (size_t)plane * NATTR * SPATIAL + s0;

    // ---- Load + transform: coalesced float4 along spatial dim ----
    // 85 attrs * 26 float4s = 2210 float4 loads per tile
    for (int f = threadIdx.x; f < NATTR * (S_TILE / 4); f += NTHREADS) {
        const int c  = f / (S_TILE / 4);
        const int sl = (f % (S_TILE / 4)) * 4;
        const float4 v = *reinterpret_cast<const float4*>(inp + (size_t)c * SPATIAL + sl);
        float r[4] = {v.x, v.y, v.z, v.w};
        #pragma unroll
        for (int k = 0; k < 4; ++k) {
            const float x = r[k];
            float o;
            if (c == 0) {
                const int sll = sl + k;
                const float gx = (float)(sll % GDIM);      // sll < 104 -> cheap
                o = (__frcp_rn(1.0f + __expf(-x)) + gx) * 8.0f;
            } else if (c == 1) {
                const int sll = sl + k;
                const float gy = (float)(y0 + sll / GDIM);
                o = (__frcp_rn(1.0f + __expf(-x)) + gy) * 8.0f;
            } else if (c == 2) {
                o = __expf(x) * aw;
            } else if (c == 3) {
                o = __expf(x) * ah;
            } else {
                o = __frcp_rn(1.0f + __expf(-x));
            }
            sm[c * SMEM_LD + sl + k] = o;
        }
    }
    __syncthreads();

    // ---- Store: the whole tile's output (104 rows * 85 attrs = 8840 floats)
    // is one contiguous, 16B-aligned run -> float4 stores, fully coalesced.
    float* outp = out + ((size_t)plane * SPATIAL + s0) * NATTR;
    for (int f = threadIdx.x; f < (S_TILE * NATTR) / 4; f += NTHREADS) {
        const int e = f * 4;
        float t[4];
        #pragma unroll
        for (int k = 0; k < 4; ++k) {
            const int ee = e + k;
            t[k] = sm[(ee % NATTR) * SMEM_LD + ee / NATTR];
        }
        *reinterpret_cast<float4*>(outp + e) = make_float4(t[0], t[1], t[2], t[3]);
    }
}

extern "C" void kernel_launch(void* const* d_in, const int* in_sizes, int n_in,
                              void* d_out, int out_size) {
    const float* x = (const float*)d_in[0];
    float* out = (float*)d_out;
    const int nblocks = 64 * 3 * TILES;     // 4992
    yolo_decode_kernel<<<nblocks, NTHREADS>>>(x, out);
}